// round 9
// baseline (speedup 1.0000x reference)
#include <cuda_runtime.h>
#include <cuda_bf16.h>
#include <cstdint>

// Problem constants
#define BB   128
#define SS   37
#define TT   2048
#define DD   256
#define STT  8
#define CC   2
#define MER  264
#define NF   74

#define NBLK 148        // = SM count; 4736 rows / 148 = 32 exactly
#define NT   512
#define RPB  32         // rows per block
#define NPOS 512        // float4 positions per row (2048/4)

// tail merge GEMV split
#define G2   6
#define Q2   66
#define KI2  (MER / G2)   // 44

// ---------------- device scratch (write-once per launch; no init needed) ----
__device__ float gA[BB * NF];                // [b][f]  row sums (owner-written)
__device__ float gNZ[NBLK * 2 * TT];         // [blk][seg][t] nz partials
__device__ unsigned long long gCtr;          // epoch barrier ticket counter

__device__ __forceinline__ float wredf(float v) {
    #pragma unroll
    for (int o = 16; o; o >>= 1) v += __shfl_xor_sync(0xffffffffu, v, o);
    return v;
}
// 3-level: lanes 0-3 hold 4 disjoint partials
__device__ __forceinline__ float wred3(float v) {
    v += __shfl_xor_sync(0xffffffffu, v, 16);
    v += __shfl_xor_sync(0xffffffffu, v, 8);
    v += __shfl_xor_sync(0xffffffffu, v, 4);
    return v;
}
__device__ __forceinline__ void pf_l2(const void* p) {
    asm volatile("prefetch.global.L2 [%0];" :: "l"(p));
}

__global__ __launch_bounds__(NT, 2)   // <=64 regs -> 2 blocks/SM capacity (barrier safety)
void fused_kernel(const float* __restrict__ x,
                  const int*   __restrict__ smask,
                  const float* __restrict__ tim,
                  const float* __restrict__ stat,
                  const float* __restrict__ Ws,   // [NF, DD]
                  const float* __restrict__ bs,
                  const float* __restrict__ Wt,   // [1, DD]
                  const float* __restrict__ bt,
                  const float* __restrict__ Wst,  // [STT, STT]
                  const float* __restrict__ bst,
                  const float* __restrict__ Wm,   // [MER, MER]
                  const float* __restrict__ bm,
                  const float* __restrict__ Wc,   // [MER, CC]
                  const float* __restrict__ bc,
                  float* __restrict__ out) {
    const int i    = blockIdx.x;
    const int tid  = threadIdx.x;
    const int w    = tid >> 5;
    const int lane = tid & 31;

    __shared__ float  sRow[RPB * 128];   // [row][q(2)][64 partials]  16 KB
    __shared__ float  sAll[80];
    __shared__ float  comb[MER];
    __shared__ float4 sH4[G2 * Q2];
    __shared__ float  sMs[16], sMt[16];
    __shared__ float  outc[CC];
    __shared__ unsigned long long sTgt;

    if (tid < CC) outc[tid] = 0.f;

    // ---- L2 prefetch of all weights (spread across grid), fire-and-forget ----
    {
        unsigned r = (unsigned)i * NT + tid;
        const unsigned LWs = (NF * DD * 4) / 128;     // 592
        const unsigned LWm = (MER * MER * 4) / 128;   // 2178
        if (r < LWs) { pf_l2((const char*)Ws + r * 128u); }
        else { r -= LWs;
        if (r < LWm) { pf_l2((const char*)Wm + r * 128u); }
        else { r -= LWm;
        if (r < 17) { pf_l2((const char*)Wc + r * 128u); }
        else { r -= 17;
        if (r < 8) { pf_l2((const char*)bs + r * 128u); }
        else { r -= 8;
        if (r < 8) { pf_l2((const char*)bt + r * 128u); }
        else { r -= 8;
        if (r < 8) { pf_l2((const char*)Wt + r * 128u); }
        else { r -= 8;
        if (r < 9) { pf_l2((const char*)bm + r * 128u); }
        else { r -= 9;
        if (r < 32) { pf_l2((const char*)stat + r * 128u); }
        else { r -= 32;
        if (r < 2) { pf_l2((const char*)Wst + r * 128u); }
        else { r -= 2;
        if (r < 1) { pf_l2((const char*)bst); }
        else { r -= 1;
        if (r < 1) { pf_l2((const char*)bc); }
        }}}}}}}}}}
    }

    // ================= Phase 1: stream 32 contiguous rows =================
    const int R0      = i * RPB;
    const int bfirst  = R0 / SS;
    const int bswitch = (bfirst + 1) * SS;  // first global row of next batch

    const float4* __restrict__ x4 = (const float4*)x;
    const int4*   __restrict__ m4 = (const int4*)smask;

    float4 nzA = make_float4(0.f, 0.f, 0.f, 0.f);
    float4 nzB = make_float4(0.f, 0.f, 0.f, 0.f);

    #pragma unroll 8
    for (int rr = 0; rr < RPB; ++rr) {
        const int r = R0 + rr;
        const float4 xv = __ldcs(x4 + (size_t)r * NPOS + tid);
        const int4   mv = __ldcs(m4 + (size_t)r * NPOS + tid);

        float ax = (xv.x + xv.y) + (xv.z + xv.w);
        float am = (float)((mv.x + mv.y) + (mv.z + mv.w));

        float4 c;
        c.x = fabsf(xv.x) + (float)mv.x;
        c.y = fabsf(xv.y) + (float)mv.y;
        c.z = fabsf(xv.z) + (float)mv.z;
        c.w = fabsf(xv.w) + (float)mv.w;
        if (r < bswitch) {
            nzA.x += c.x; nzA.y += c.y; nzA.z += c.z; nzA.w += c.w;
        } else {
            nzB.x += c.x; nzB.y += c.y; nzB.z += c.z; nzB.w += c.w;
        }

        ax = wred3(ax);
        am = wred3(am);
        if (lane < 4) {
            sRow[rr * 128 +      w * 4 + lane] = ax;
            sRow[rr * 128 + 64 + w * 4 + lane] = am;
        }
    }

    // write-once nz partials (seg1 slice may be unused; never read then)
    {
        float4* dA = (float4*)&gNZ[(size_t)(i * 2 + 0) * TT];
        float4* dB = (float4*)&gNZ[(size_t)(i * 2 + 1) * TT];
        dA[tid] = nzA;
        dB[tid] = nzB;
    }
    __syncthreads();

    // combine row partials -> gA (owner-written, fixed order, no atomics)
    if (tid < 64) {
        const int rr = tid >> 1, q = tid & 1;
        const float4* p = (const float4*)&sRow[rr * 128 + q * 64];
        float acc = 0.f;
        #pragma unroll
        for (int u = 0; u < 16; ++u) {
            const float4 v = p[u];
            acc += (v.x + v.y) + (v.z + v.w);
        }
        const int r = R0 + rr, bb = r / SS, s = r - bb * SS;
        gA[bb * NF + q * SS + s] = acc;
    }

    // ================= epoch spin barrier (all 148 blocks co-resident) =====
    __threadfence();
    __syncthreads();
    if (tid == 0) {
        unsigned long long t = atomicAdd(&gCtr, 1ULL);
        sTgt = (t / NBLK + 1ULL) * (unsigned long long)NBLK;
    }
    __syncthreads();
    if (i >= BB) return;              // blocks 128..147: no tail work
    if (tid == 0) {
        volatile unsigned long long* vc = &gCtr;
        while (*vc < sTgt) { }
    }
    __syncthreads();
    __threadfence();

    // ================= Phase 2: tail for batch b = i =======================
    // nz across contributing blocks (fixed order), mask bits, msum/tmsum
    {
        const int j0 = (SS * i) / RPB;
        const int j1 = (SS * i + SS - 1) / RPB;
        float4 nzv = make_float4(0.f, 0.f, 0.f, 0.f);
        for (int j = j0; j <= j1; ++j) {
            const int bfj = (RPB * j) / SS;
            const int seg = i - bfj;  // 0 or 1
            const float4 v = *(const float4*)&gNZ[(size_t)(j * 2 + seg) * TT + tid * 4];
            nzv.x += v.x; nzv.y += v.y; nzv.z += v.z; nzv.w += v.w;
        }
        const float4 tv = ((const float4*)(tim + (size_t)i * TT))[tid];
        float ms = 0.f, tm = 0.f;
        if (nzv.x > 0.f) { ms += 1.f; tm += tv.x; }
        if (nzv.y > 0.f) { ms += 1.f; tm += tv.y; }
        if (nzv.z > 0.f) { ms += 1.f; tm += tv.z; }
        if (nzv.w > 0.f) { ms += 1.f; tm += tv.w; }
        ms = wredf(ms);
        tm = wredf(tm);
        if (lane == 0) { sMs[w] = ms; sMt[w] = tm; }
    }
    __syncthreads();

    if (tid < NF) sAll[tid] = gA[i * NF + tid];
    if (tid == NF || tid == NF + 1) {
        const float* src = (tid == NF) ? sMs : sMt;
        float acc = 0.f;
        #pragma unroll
        for (int w2 = 0; w2 < 16; ++w2) acc += src[w2];
        sAll[tid] = acc;
    }
    __syncthreads();

    const float msum  = sAll[74];
    const float tmsum = sAll[75];
    const float inv   = 1.f / fmaxf(msum, 1e-9f);

    // ---- A: comb[MER] ----
    if (tid < DD) {
        float acc = 0.f;
        #pragma unroll 8
        for (int f = 0; f < NF; ++f) acc += sAll[f] * Ws[f * DD + tid];
        acc += msum * (bs[tid] + bt[tid]) + tmsum * Wt[tid];
        comb[tid] = acc * inv;
    } else if (tid < MER) {
        const int j = tid - DD;
        float acc = bst[j];
        #pragma unroll
        for (int q = 0; q < STT; ++q) acc += stat[i * STT + q] * Wst[q * STT + j];
        comb[tid] = acc;
    }
    __syncthreads();

    // ---- B: merge GEMV split-i, float4 columns ----
    if (tid < G2 * Q2) {
        const int q  = tid % Q2;
        const int gg = tid / Q2;
        const float4* __restrict__ Wm4 = (const float4*)Wm;
        float4 acc = make_float4(0.f, 0.f, 0.f, 0.f);
        #pragma unroll
        for (int kk = 0; kk < KI2; ++kk) {
            const int ii = gg * KI2 + kk;
            const float  c  = comb[ii];
            const float4 wv = Wm4[ii * Q2 + q];
            acc.x += c * wv.x;
            acc.y += c * wv.y;
            acc.z += c * wv.z;
            acc.w += c * wv.w;
        }
        sH4[gg * Q2 + q] = acc;
    }
    __syncthreads();

    // ---- C: reduce, ReLU, classifier ----
    float p0 = 0.f, p1 = 0.f;
    if (tid < MER) {
        const float* sH = (const float*)sH4;
        float t = bm[tid];
        #pragma unroll
        for (int gg = 0; gg < G2; ++gg) t += sH[gg * MER + tid];
        const float h = fmaxf(t, 0.f);
        p0 = h * Wc[tid * CC + 0];
        p1 = h * Wc[tid * CC + 1];
    }
    p0 = wredf(p0);
    p1 = wredf(p1);
    if (lane == 0) {
        atomicAdd(&outc[0], p0);
        atomicAdd(&outc[1], p1);
    }
    __syncthreads();

    if (tid < CC) out[i * CC + tid] = outc[tid] + bc[tid];
}

// ---------------- launch ----------------
extern "C" void kernel_launch(void* const* d_in, const int* in_sizes, int n_in,
                              void* d_out, int out_size) {
    const float* x     = (const float*)d_in[0];
    const float* stat  = (const float*)d_in[1];
    const float* tim   = (const float*)d_in[2];
    const int*   smask = (const int*)  d_in[3];
    const float* Ws    = (const float*)d_in[4];
    const float* bs    = (const float*)d_in[5];
    const float* Wt    = (const float*)d_in[6];
    const float* bt    = (const float*)d_in[7];
    const float* Wst   = (const float*)d_in[8];
    const float* bst   = (const float*)d_in[9];
    const float* Wm    = (const float*)d_in[10];
    const float* bm    = (const float*)d_in[11];
    const float* Wc    = (const float*)d_in[12];
    const float* bc    = (const float*)d_in[13];
    float* out = (float*)d_out;

    fused_kernel<<<NBLK, NT>>>(x, smask, tim, stat, Ws, bs, Wt, bt,
                               Wst, bst, Wm, bm, Wc, bc, out);
}